// round 1
// baseline (speedup 1.0000x reference)
#include <cuda_runtime.h>
#include <cuda_bf16.h>
#include <math.h>

// Problem constants
#define B_  8
#define S_  16
#define C_  32
#define P_  64
#define E_  768
#define M_  512          // S*C
#define L_  32768        // M*P
#define NE_ 1000000
#define EV_ 192          // E/4 float4s

// Scratch (device globals; no allocations allowed)
__device__ float g_sum1[B_ * M_];
__device__ float g_cand[B_ * M_];
__device__ int   g_patch_q[B_ * M_];
__device__ float g_patch_v[B_ * M_];
__device__ float g_max[B_];
__device__ float g_invden[B_];
__device__ float g_bg[B_];

// ---------------------------------------------------------------------------
// Kernel 1: fused embedding-bag + dot with span vector.
// One block per (b, m) segment. sum1[b,m] = sum_j att_j * dot(table[id_j], span[b, m%S])
// ---------------------------------------------------------------------------
__global__ __launch_bounds__(256) void bag_dot_kernel(
    const float* __restrict__ span_embs,   // (B,S,E)
    const int*   __restrict__ ids,         // (B,L)
    const int*   __restrict__ offs,        // (B,M)
    const float* __restrict__ att,         // (B,L)
    const float* __restrict__ table)       // (T,E)
{
    const int seg = blockIdx.x;            // 0 .. B*M-1
    const int b = seg >> 9;                // /512
    const int m = seg & (M_ - 1);

    __shared__ float4 sv[EV_];
    const int tid = threadIdx.x;
    const float4* sp = reinterpret_cast<const float4*>(
        span_embs + ((size_t)b * S_ + (m & (S_ - 1))) * E_);
    if (tid < EV_) sv[tid] = sp[tid];
    __syncthreads();

    const int start = offs[b * M_ + m];
    const int end   = (m == M_ - 1) ? L_ : offs[b * M_ + m + 1];

    const int lane = tid & 31;
    const int w    = tid >> 5;             // 8 warps

    float acc = 0.f;
    for (int j = start + w; j < end; j += 8) {
        const int   id = ids[(size_t)b * L_ + j];
        const float a  = att[(size_t)b * L_ + j];
        const float4* row = reinterpret_cast<const float4*>(table + (size_t)id * E_);
        float d = 0.f;
        #pragma unroll
        for (int k = 0; k < 6; k++) {
            float4 r = row[lane + 32 * k];
            float4 s = sv[lane + 32 * k];
            d += r.x * s.x + r.y * s.y + r.z * s.z + r.w * s.w;
        }
        acc += a * d;
    }
    #pragma unroll
    for (int o = 16; o; o >>= 1) acc += __shfl_xor_sync(0xffffffffu, acc, o);

    __shared__ float wsum[8];
    if (lane == 0) wsum[w] = acc;
    __syncthreads();
    if (tid == 0) {
        float t = 0.f;
        #pragma unroll
        for (int i = 0; i < 8; i++) t += wsum[i];
        g_sum1[seg] = t;
    }
}

// ---------------------------------------------------------------------------
// Kernel 2: span_scores + softmax over S + softmax over M -> cand_scores
// One block (512 threads) per batch. tid = s*32 + c.
// ---------------------------------------------------------------------------
__global__ __launch_bounds__(512) void score_kernel(
    const float* __restrict__ span_embs,
    const float* __restrict__ span_W,
    const float* __restrict__ span_b)
{
    const int b = blockIdx.x;
    const int tid = threadIdx.x;           // 512
    const int w = tid >> 5, lane = tid & 31;
    const int s = tid >> 5, c = tid & 31;  // layout matches m = s*C + c

    __shared__ float s1[M_];
    __shared__ float sscore[S_];
    __shared__ float colmax[C_], colrs[C_];
    __shared__ float redf[16];

    s1[tid] = g_sum1[b * M_ + tid];

    // span_scores[b, w]: warp w computes dot(span_embs[b,w], span_W) + span_b
    const float* v = span_embs + ((size_t)b * S_ + w) * E_;
    float d = 0.f;
    for (int k = lane; k < E_; k += 32) d += v[k] * span_W[k];
    #pragma unroll
    for (int o = 16; o; o >>= 1) d += __shfl_xor_sync(0xffffffffu, d, o);
    if (lane == 0) sscore[w] = d + span_b[0];
    __syncthreads();

    // softmax over s (16 values) per column c: threads 0..31 each own a column
    if (tid < C_) {
        float mx = -1e30f;
        #pragma unroll
        for (int ss = 0; ss < S_; ss++) mx = fmaxf(mx, s1[ss * C_ + tid]);
        float sm = 0.f;
        #pragma unroll
        for (int ss = 0; ss < S_; ss++) sm += __expf(s1[ss * C_ + tid] - mx);
        colmax[tid] = mx;
        colrs[tid] = 1.f / sm;
    }
    __syncthreads();

    float sm1 = __expf(s1[tid] - colmax[c]) * colrs[c];
    float m2  = sscore[s] * sm1;

    // block softmax over all 512 values
    float mx = m2;
    #pragma unroll
    for (int o = 16; o; o >>= 1) mx = fmaxf(mx, __shfl_xor_sync(0xffffffffu, mx, o));
    if (lane == 0) redf[w] = mx;
    __syncthreads();
    if (tid == 0) {
        float t = redf[0];
        #pragma unroll
        for (int i = 1; i < 16; i++) t = fmaxf(t, redf[i]);
        redf[0] = t;
    }
    __syncthreads();
    const float gmx = redf[0];
    __syncthreads();

    float e = __expf(m2 - gmx);
    float ssum = e;
    #pragma unroll
    for (int o = 16; o; o >>= 1) ssum += __shfl_xor_sync(0xffffffffu, ssum, o);
    if (lane == 0) redf[w] = ssum;
    __syncthreads();
    if (tid == 0) {
        float t = 0.f;
        #pragma unroll
        for (int i = 0; i < 16; i++) t += redf[i];
        redf[0] = 1.f / t;
    }
    __syncthreads();
    g_cand[b * M_ + tid] = e * redf[0];
}

// ---------------------------------------------------------------------------
// Kernel 3: scatter-dedupe + analytic softmax stats over NE entries.
// One block (512 threads) per batch.
// ---------------------------------------------------------------------------
__global__ __launch_bounds__(512) void stats_kernel(const int* __restrict__ qids)
{
    const int b = blockIdx.x;
    const int tid = threadIdx.x;
    const int w = tid >> 5, lane = tid & 31;

    __shared__ int   q[M_];
    __shared__ float v[M_];
    __shared__ float redf[16];
    __shared__ int   redi[16];

    q[tid] = qids[b * M_ + tid];
    v[tid] = g_cand[b * M_ + tid];
    __syncthreads();

    const int myq = q[tid];
    const bool valid = (myq < NE_);        // qid == NE is dropped by reference
    bool first = valid;
    float acc = 0.f;
    if (valid) {
        for (int i = 0; i < M_; i++) {
            if (q[i] == myq) {
                if (i < tid) first = false;
                acc += v[i];               // accumulate scatter collisions
            }
        }
    }
    if (!first) acc = 0.f;

    // max over first-occurrence values (zeros exist in the full array, so clamp at 0)
    float mx = first ? acc : 0.f;
    #pragma unroll
    for (int o = 16; o; o >>= 1) mx = fmaxf(mx, __shfl_xor_sync(0xffffffffu, mx, o));
    if (lane == 0) redf[w] = mx;
    __syncthreads();
    if (tid == 0) {
        float t = 0.f;
        #pragma unroll
        for (int i = 0; i < 16; i++) t = fmaxf(t, redf[i]);
        redf[0] = t;
    }
    __syncthreads();
    const float maxv = redf[0];
    __syncthreads();

    float se = first ? expf(acc - maxv) : 0.f;
    int   c1 = first ? 1 : 0;
    #pragma unroll
    for (int o = 16; o; o >>= 1) {
        se += __shfl_xor_sync(0xffffffffu, se, o);
        c1 += __shfl_xor_sync(0xffffffffu, c1, o);
    }
    if (lane == 0) { redf[w] = se; redi[w] = c1; }
    __syncthreads();
    if (tid == 0) {
        float ss = 0.f; int cc = 0;
        #pragma unroll
        for (int i = 0; i < 16; i++) { ss += redf[i]; cc += redi[i]; }
        const float denom = (float)(NE_ - cc) * expf(-maxv) + ss;
        const float inv = 1.f / denom;
        g_max[b] = maxv;
        g_invden[b] = inv;
        g_bg[b] = expf(-maxv) * inv;
    }
    g_patch_q[b * M_ + tid] = first ? myq : -1;
    g_patch_v[b * M_ + tid] = acc;
}

// ---------------------------------------------------------------------------
// Kernel 4: fill output with per-batch background constant (pure 32MB write)
// ---------------------------------------------------------------------------
__global__ __launch_bounds__(256) void fill_kernel(float4* __restrict__ out)
{
    const size_t i = (size_t)blockIdx.x * blockDim.x + threadIdx.x;
    if (i >= (size_t)B_ * NE_ / 4) return;
    const int b = (int)(i / (NE_ / 4));
    const float bg = g_bg[b];
    out[i] = make_float4(bg, bg, bg, bg);
}

// ---------------------------------------------------------------------------
// Kernel 5: patch candidate positions
// ---------------------------------------------------------------------------
__global__ __launch_bounds__(256) void patch_kernel(float* __restrict__ out)
{
    const int k = blockIdx.x * blockDim.x + threadIdx.x;
    if (k >= B_ * M_) return;
    const int b = k >> 9;
    const int qi = g_patch_q[k];
    if (qi >= 0)
        out[(size_t)b * NE_ + qi] = expf(g_patch_v[k] - g_max[b]) * g_invden[b];
}

// ---------------------------------------------------------------------------
extern "C" void kernel_launch(void* const* d_in, const int* in_sizes, int n_in,
                              void* d_out, int out_size)
{
    // metadata order:
    // 0 span_embs (B,S,E) f32 | 1 triplet_ids_tr (B,L) i32 | 2 offsets_tr (B,M) i32
    // 3 attention_tr (B,L) f32 | 4 qid_inds (B,M) i32 | 5 emb_weight (T,E) f32
    // 6 span_W (E,1) f32 | 7 span_b (1,) f32
    const float* span_embs = (const float*)d_in[0];
    const int*   ids       = (const int*)d_in[1];
    const int*   offs      = (const int*)d_in[2];
    const float* att       = (const float*)d_in[3];
    const int*   qids      = (const int*)d_in[4];
    const float* table     = (const float*)d_in[5];
    const float* span_W    = (const float*)d_in[6];
    const float* span_b    = (const float*)d_in[7];
    float* out = (float*)d_out;

    bag_dot_kernel<<<B_ * M_, 256>>>(span_embs, ids, offs, att, table);
    score_kernel<<<B_, 512>>>(span_embs, span_W, span_b);
    stats_kernel<<<B_, 512>>>(qids);
    const int n4 = B_ * NE_ / 4;
    fill_kernel<<<(n4 + 255) / 256, 256>>>((float4*)out);
    patch_kernel<<<(B_ * M_ + 255) / 256, 256>>>(out);
}